// round 1
// baseline (speedup 1.0000x reference)
#include <cuda_runtime.h>
#include <cstdint>

// Problem constants (fixed by the dataset)
#define NMAX   500000
#define EMB    32
#define IN_DIM 65

// Scratch (allocation-free rule: __device__ globals)
__device__ __align__(128) float g_deg[NMAX];            // degree, then dinv in-place
__device__ __align__(128) float g_agg[(size_t)NMAX * EMB]; // 64 MB accumulator

// ---------------------------------------------------------------------------
// K1: init deg = 1.0, out[g] = b_out[0]
// ---------------------------------------------------------------------------
__global__ void k_init(float* __restrict__ out, const float* __restrict__ b_out,
                       int N, int G) {
    int i = blockIdx.x * blockDim.x + threadIdx.x;
    if (i < N) g_deg[i] = 1.0f;
    if (i < G) out[i] = b_out[0];
}

// ---------------------------------------------------------------------------
// K2: deg[dst] += 1 per edge (RED, no return)
// ---------------------------------------------------------------------------
__global__ void k_deg(const int* __restrict__ dst, int E) {
    int e = blockIdx.x * blockDim.x + threadIdx.x;
    if (e < E) atomicAdd(&g_deg[dst[e]], 1.0f);
}

// ---------------------------------------------------------------------------
// K3: dinv = rsqrt(deg) (in place) ; agg[i][:] = dinv^2 * W[x[i]][:]
//     (initializes the full agg array -> no separate zeroing pass)
// ---------------------------------------------------------------------------
__global__ void k_self(const int* __restrict__ x, const float* __restrict__ W, int N) {
    int i = blockIdx.x * blockDim.x + threadIdx.x;
    if (i >= N) return;
    float dinv = rsqrtf(g_deg[i]);
    g_deg[i] = dinv;                       // reused as dinv by K4
    float s = dinv * dinv;
    const float4* Wr = reinterpret_cast<const float4*>(W + (size_t)x[i] * EMB);
    float4* a = reinterpret_cast<float4*>(g_agg + (size_t)i * EMB);
#pragma unroll
    for (int j = 0; j < EMB / 4; j++) {
        float4 w = __ldg(&Wr[j]);
        a[j] = make_float4(w.x * s, w.y * s, w.z * s, w.w * s);
    }
}

// ---------------------------------------------------------------------------
// K4: edge scatter: agg[dst] += dinv[src]*dinv[dst] * W[x[src]]
//     Warp = 4 edges, 8 lanes per edge, one red.v4.f32 per lane (128B/edge).
//     W staged in shared memory (8.3 KB).
// ---------------------------------------------------------------------------
__global__ void k_edge(const int* __restrict__ src, const int* __restrict__ dst,
                       const int* __restrict__ x, const float* __restrict__ W, int E) {
    __shared__ __align__(16) float sW[IN_DIM * EMB];
    for (int t = threadIdx.x; t < IN_DIM * EMB; t += blockDim.x) sW[t] = W[t];
    __syncthreads();

    int lane = threadIdx.x & 31;
    int sub  = lane >> 3;        // which of 4 edges in this warp
    int f    = lane & 7;         // float4 index within the 32-wide row
    int warp = (blockIdx.x * blockDim.x + threadIdx.x) >> 5;
    int nwarps = (gridDim.x * blockDim.x) >> 5;

    for (int e = warp * 4 + sub; e < E; e += nwarps * 4) {
        int s = src[e];
        int d = dst[e];
        float norm = g_deg[s] * g_deg[d];          // dinv[s]*dinv[d]
        int xs = x[s];
        float4 w = *reinterpret_cast<const float4*>(&sW[xs * EMB + f * 4]);
        float* addr = g_agg + (size_t)d * EMB + f * 4;
        asm volatile(
            "red.global.add.v4.f32 [%0], {%1, %2, %3, %4};"
            :: "l"(addr), "f"(w.x * norm), "f"(w.y * norm),
               "f"(w.z * norm), "f"(w.w * norm)
            : "memory");
    }
}

// ---------------------------------------------------------------------------
// K5: per node: s = sum_j tanh(agg[i][j] + b_conv[j]) * W_out[j]
//     then out[batch[i]] += s  (batch sorted -> mostly-local atomics)
// ---------------------------------------------------------------------------
__device__ __forceinline__ float tanha(float v) {
    float r;
    asm("tanh.approx.f32 %0, %1;" : "=f"(r) : "f"(v));
    return r;
}

__global__ void k_pool(const int* __restrict__ batch,
                       const float* __restrict__ b_conv,
                       const float* __restrict__ W_out,
                       float* __restrict__ out, int N) {
    __shared__ float sb[EMB];
    __shared__ float sw[EMB];
    if (threadIdx.x < EMB) {
        sb[threadIdx.x] = b_conv[threadIdx.x];
        sw[threadIdx.x] = W_out[threadIdx.x];
    }
    __syncthreads();

    int i = blockIdx.x * blockDim.x + threadIdx.x;
    if (i >= N) return;

    const float4* a = reinterpret_cast<const float4*>(g_agg + (size_t)i * EMB);
    float acc = 0.f;
#pragma unroll
    for (int j = 0; j < EMB / 4; j++) {
        float4 v = a[j];
        acc += tanha(v.x + sb[4 * j + 0]) * sw[4 * j + 0];
        acc += tanha(v.y + sb[4 * j + 1]) * sw[4 * j + 1];
        acc += tanha(v.z + sb[4 * j + 2]) * sw[4 * j + 2];
        acc += tanha(v.w + sb[4 * j + 3]) * sw[4 * j + 3];
    }
    atomicAdd(&out[batch[i]], acc);
}

// ---------------------------------------------------------------------------
// Launch
// Inputs (metadata order): 0:x[N] i32, 1:edge_index[2*E] i32, 2:batch_index[N] i32,
//                          3:W[65*32] f32, 4:b_conv[32] f32, 5:W_out[32] f32, 6:b_out[1] f32
// Output: out[G] f32
// ---------------------------------------------------------------------------
extern "C" void kernel_launch(void* const* d_in, const int* in_sizes, int n_in,
                              void* d_out, int out_size) {
    const int*   x     = (const int*)d_in[0];
    const int*   eidx  = (const int*)d_in[1];
    const int*   batch = (const int*)d_in[2];
    const float* W     = (const float*)d_in[3];
    const float* bconv = (const float*)d_in[4];
    const float* Wout  = (const float*)d_in[5];
    const float* bout  = (const float*)d_in[6];
    float* out = (float*)d_out;

    int N = in_sizes[0];
    int E = in_sizes[1] / 2;
    int G = out_size;

    const int* src = eidx;
    const int* dst = eidx + E;

    int TB = 256;
    int initN = N > G ? N : G;

    k_init<<<(initN + TB - 1) / TB, TB>>>(out, bout, N, G);
    k_deg <<<(E + TB - 1) / TB, TB>>>(dst, E);
    k_self<<<(N + TB - 1) / TB, TB>>>(x, W, N);

    // K4: persistent-ish grid; each warp covers 4 edges per iteration.
    int edge_blocks = 148 * 8;   // ~9472 warps -> ~53 iterations over 2M edges
    k_edge<<<edge_blocks, TB>>>(src, dst, x, W, E);

    k_pool<<<(N + TB - 1) / TB, TB>>>(batch, bconv, Wout, out, N);
}

// round 2
// speedup vs baseline: 1.3737x; 1.3737x over previous
#include <cuda_runtime.h>
#include <cstdint>

// Problem constants (fixed by the dataset)
#define NMAX   500000
#define EMAX   2000000
#define EMB    32
#define IN_DIM 65
#define TB     256
#define MAXBLK 2048          // supports N up to 524288 for the scan

// Scratch (allocation-free rule: __device__ globals) — ~24 MB total
__device__ __align__(128) int  g_cnt[NMAX];     // indegree (excl. self-loop)
__device__ __align__(128) int  g_rank[EMAX];    // rank of edge within dst segment
__device__ __align__(128) int  g_base[NMAX];    // CSR segment base (excl. scan of cnt)
__device__ __align__(128) int  g_bsum[MAXBLK];  // per-block sums -> exclusive bases
__device__ __align__(128) int2 g_packed[NMAX];  // {dinv as bits, x}
__device__ __align__(128) int  g_elist[EMAX];   // CSR edge list (src ids)

// ---------------------------------------------------------------------------
// K1: zero counts, out[g] = b_out[0]
// ---------------------------------------------------------------------------
__global__ void k_init(float* __restrict__ out, const float* __restrict__ b_out,
                       int N, int G) {
    int i = blockIdx.x * blockDim.x + threadIdx.x;
    if (i < N) g_cnt[i] = 0;
    if (i < G) out[i] = b_out[0];
}

// ---------------------------------------------------------------------------
// K2: count indegree; the returned old count is this edge's rank in its segment
// ---------------------------------------------------------------------------
__global__ void k_deg(const int* __restrict__ dst, int E) {
    int e = blockIdx.x * blockDim.x + threadIdx.x;
    if (e < E) {
        int r = atomicAdd(&g_cnt[dst[e]], 1);
        g_rank[e] = r;
    }
}

// ---------------------------------------------------------------------------
// S1: per-block sums of counts
// ---------------------------------------------------------------------------
__global__ void k_scan1(int N) {
    __shared__ int s[TB];
    int i = blockIdx.x * TB + threadIdx.x;
    s[threadIdx.x] = (i < N) ? g_cnt[i] : 0;
    __syncthreads();
#pragma unroll
    for (int off = TB / 2; off > 0; off >>= 1) {
        if (threadIdx.x < off) s[threadIdx.x] += s[threadIdx.x + off];
        __syncthreads();
    }
    if (threadIdx.x == 0) g_bsum[blockIdx.x] = s[0];
}

// ---------------------------------------------------------------------------
// S2: exclusive scan of up to 2048 block sums in a single 1024-thread block
// ---------------------------------------------------------------------------
__global__ void k_scan2(int nb) {
    __shared__ int s[1024];
    int t = threadIdx.x;
    int v0 = (2 * t     < nb) ? g_bsum[2 * t]     : 0;
    int v1 = (2 * t + 1 < nb) ? g_bsum[2 * t + 1] : 0;
    int tsum = v0 + v1;
    s[t] = tsum;
    __syncthreads();
    for (int off = 1; off < 1024; off <<= 1) {
        int v = (t >= off) ? s[t - off] : 0;
        __syncthreads();
        s[t] += v;
        __syncthreads();
    }
    int excl = s[t] - tsum;                 // exclusive prefix of this thread's pair
    if (2 * t     < nb) g_bsum[2 * t]     = excl;
    if (2 * t + 1 < nb) g_bsum[2 * t + 1] = excl + v0;
}

// ---------------------------------------------------------------------------
// S3: per-element exclusive scan within block + block base -> g_base
//     also compute dinv = rsqrt(1 + cnt) and pack {dinv, x}
// ---------------------------------------------------------------------------
__global__ void k_scan3(const int* __restrict__ x, int N) {
    __shared__ int s[TB];
    int i = blockIdx.x * TB + threadIdx.x;
    int t = threadIdx.x;
    int c = (i < N) ? g_cnt[i] : 0;
    s[t] = c;
    __syncthreads();
    for (int off = 1; off < TB; off <<= 1) {
        int v = (t >= off) ? s[t - off] : 0;
        __syncthreads();
        s[t] += v;
        __syncthreads();
    }
    if (i < N) {
        g_base[i] = g_bsum[blockIdx.x] + (s[t] - c);   // exclusive
        float dinv = rsqrtf(1.0f + (float)c);
        g_packed[i] = make_int2(__float_as_int(dinv), x[i]);
    }
}

// ---------------------------------------------------------------------------
// K4: scatter src ids into CSR slots: elist[base[d] + rank[e]] = src[e]
// ---------------------------------------------------------------------------
__global__ void k_build(const int* __restrict__ src, const int* __restrict__ dst,
                        int E) {
    int e = blockIdx.x * blockDim.x + threadIdx.x;
    if (e < E) {
        int d   = dst[e];
        int pos = g_base[d] + g_rank[e];
        g_elist[pos] = src[e];
    }
}

// ---------------------------------------------------------------------------
// K5: per node: gather in-edges, register-accumulate, tanh, dot, pool
//     agg[i] = dinv_i * ( dinv_i*W[x_i] + sum_e dinv_s*W[x_s] ) + b_conv
// ---------------------------------------------------------------------------
__device__ __forceinline__ float tanha(float v) {
    float r;
    asm("tanh.approx.f32 %0, %1;" : "=f"(r) : "f"(v));
    return r;
}

#define WPITCH 33   // pad rows so random-row smem access spreads banks

__global__ void k_aggpool(const int* __restrict__ batch,
                          const float* __restrict__ W,
                          const float* __restrict__ b_conv,
                          const float* __restrict__ W_out,
                          float* __restrict__ out, int N) {
    __shared__ float sW[IN_DIM * WPITCH];
    __shared__ float sb[EMB];
    __shared__ float so[EMB];
    for (int t = threadIdx.x; t < IN_DIM * EMB; t += blockDim.x) {
        int r = t / EMB, cCol = t % EMB;
        sW[r * WPITCH + cCol] = W[t];
    }
    if (threadIdx.x < EMB) {
        sb[threadIdx.x] = b_conv[threadIdx.x];
        so[threadIdx.x] = W_out[threadIdx.x];
    }
    __syncthreads();

    int i = blockIdx.x * blockDim.x + threadIdx.x;
    if (i >= N) return;

    int2 p = g_packed[i];
    float dinv = __int_as_float(p.x);
    int   xi   = p.y;
    int   b0   = g_base[i];
    int   cnt  = g_cnt[i];

    float acc[EMB];
    {
        const float* row = &sW[xi * WPITCH];
#pragma unroll
        for (int j = 0; j < EMB; j++) acc[j] = dinv * row[j];
    }
    for (int k = 0; k < cnt; k++) {
        int  s  = g_elist[b0 + k];
        int2 ps = g_packed[s];
        float ds = __int_as_float(ps.x);
        const float* row = &sW[ps.y * WPITCH];
#pragma unroll
        for (int j = 0; j < EMB; j++) acc[j] += ds * row[j];
    }

    float res = 0.f;
#pragma unroll
    for (int j = 0; j < EMB; j++)
        res += tanha(acc[j] * dinv + sb[j]) * so[j];

    atomicAdd(&out[batch[i]], res);
}

// ---------------------------------------------------------------------------
// Launch
// Inputs: 0:x[N] i32, 1:edge_index[2E] i32, 2:batch[N] i32,
//         3:W[65*32] f32, 4:b_conv[32] f32, 5:W_out[32] f32, 6:b_out[1] f32
// Output: out[G] f32
// ---------------------------------------------------------------------------
extern "C" void kernel_launch(void* const* d_in, const int* in_sizes, int n_in,
                              void* d_out, int out_size) {
    const int*   x     = (const int*)d_in[0];
    const int*   eidx  = (const int*)d_in[1];
    const int*   batch = (const int*)d_in[2];
    const float* W     = (const float*)d_in[3];
    const float* bconv = (const float*)d_in[4];
    const float* Wout  = (const float*)d_in[5];
    const float* bout  = (const float*)d_in[6];
    float* out = (float*)d_out;

    int N = in_sizes[0];
    int E = in_sizes[1] / 2;
    int G = out_size;

    const int* src = eidx;
    const int* dst = eidx + E;

    int nb    = (N + TB - 1) / TB;       // scan blocks
    int initN = N > G ? N : G;

    k_init <<<(initN + TB - 1) / TB, TB>>>(out, bout, N, G);
    k_deg  <<<(E + TB - 1) / TB, TB>>>(dst, E);
    k_scan1<<<nb, TB>>>(N);
    k_scan2<<<1, 1024>>>(nb);
    k_scan3<<<nb, TB>>>(x, N);
    k_build<<<(E + TB - 1) / TB, TB>>>(src, dst, E);
    k_aggpool<<<nb, TB>>>(batch, W, bconv, Wout, out, N);
}

// round 4
// speedup vs baseline: 1.4662x; 1.0673x over previous
#include <cuda_runtime.h>
#include <cstdint>

// Problem constants (fixed by the dataset)
#define NMAX   500000
#define EMAX   2000000
#define EMB    32
#define IN_DIM 65
#define TB     256

// Scratch (allocation-free rule: __device__ globals)
__device__ int g_total;
__device__ __align__(128) int  g_cnt[NMAX];     // indegree (excl. self-loop)
__device__ __align__(128) int  g_base[NMAX];    // CSR base; after k_build: segment END
__device__ __align__(128) int2 g_packed[NMAX];  // {dinv bits, x}
__device__ __align__(128) int  g_elist[EMAX];   // CSR edge list (src ids)

// ---------------------------------------------------------------------------
// K1: zero counts, out[g] = b_out[0], reset bump allocator
// ---------------------------------------------------------------------------
__global__ void k_init(float* __restrict__ out, const float* __restrict__ b_out,
                       int N, int G) {
    int i = blockIdx.x * blockDim.x + threadIdx.x;
    if (i < N) g_cnt[i] = 0;
    if (i < G) out[i] = b_out[0];
    if (i == 0) g_total = 0;
}

// ---------------------------------------------------------------------------
// K2: indegree count (pure RED, no return). 4 edges/thread via int4.
// ---------------------------------------------------------------------------
__global__ void k_deg(const int* __restrict__ dst, int E) {
    int t = blockIdx.x * blockDim.x + threadIdx.x;
    int e = t * 4;
    if (e + 3 < E) {
        int4 d = *reinterpret_cast<const int4*>(dst + e);
        atomicAdd(&g_cnt[d.x], 1);
        atomicAdd(&g_cnt[d.y], 1);
        atomicAdd(&g_cnt[d.z], 1);
        atomicAdd(&g_cnt[d.w], 1);
    } else {
        for (int k = e; k < E; k++) atomicAdd(&g_cnt[dst[k]], 1);
    }
}

// ---------------------------------------------------------------------------
// K3: fused allocation: block scan of counts + one atomic block-base claim.
//     Also computes dinv = rsqrt(1+cnt) and packs {dinv, x}.
//     (Block ordering is nondeterministic but each node's segment is
//      contiguous and self-consistent -> result unchanged within fp tolerance.)
// ---------------------------------------------------------------------------
__global__ void k_alloc(const int* __restrict__ x, int N) {
    __shared__ int swarp[TB / 32];
    __shared__ int sbb;
    int i    = blockIdx.x * TB + threadIdx.x;
    int lane = threadIdx.x & 31;
    int wid  = threadIdx.x >> 5;

    int c = (i < N) ? g_cnt[i] : 0;
    int incl = c;
#pragma unroll
    for (int o = 1; o < 32; o <<= 1) {
        int v = __shfl_up_sync(0xffffffffu, incl, o);
        if (lane >= o) incl += v;
    }
    if (lane == 31) swarp[wid] = incl;
    __syncthreads();
    if (threadIdx.x == 0) {
        int s = 0;
#pragma unroll
        for (int w = 0; w < TB / 32; w++) { int v = swarp[w]; swarp[w] = s; s += v; }
        sbb = atomicAdd(&g_total, s);
    }
    __syncthreads();
    if (i < N) {
        g_base[i] = sbb + swarp[wid] + (incl - c);   // exclusive base
        float dinv = rsqrtf(1.0f + (float)c);
        g_packed[i] = make_int2(__float_as_int(dinv), x[i]);
    }
}

// ---------------------------------------------------------------------------
// K4: slot-claim + scatter: pos = base[d]++ ; elist[pos] = src.
//     After this kernel g_base[d] holds the segment END.
// ---------------------------------------------------------------------------
__global__ void k_build(const int* __restrict__ src, const int* __restrict__ dst,
                        int E) {
    int t = blockIdx.x * blockDim.x + threadIdx.x;
    int e = t * 4;
    if (e + 3 < E) {
        int4 s4 = *reinterpret_cast<const int4*>(src + e);
        int4 d4 = *reinterpret_cast<const int4*>(dst + e);
        int p;
        p = atomicAdd(&g_base[d4.x], 1); g_elist[p] = s4.x;
        p = atomicAdd(&g_base[d4.y], 1); g_elist[p] = s4.y;
        p = atomicAdd(&g_base[d4.z], 1); g_elist[p] = s4.z;
        p = atomicAdd(&g_base[d4.w], 1); g_elist[p] = s4.w;
    } else {
        for (int k = e; k < E; k++) {
            int p = atomicAdd(&g_base[dst[k]], 1);
            g_elist[p] = src[k];
        }
    }
}

// ---------------------------------------------------------------------------
// K5: per node: gather in-edges, register-accumulate, tanh, dot, pool
// ---------------------------------------------------------------------------
__device__ __forceinline__ float tanha(float v) {
    float r;
    asm("tanh.approx.f32 %0, %1;" : "=f"(r) : "f"(v));
    return r;
}

#define WPITCH 33   // pad rows so random-row smem access spreads banks

__global__ void k_aggpool(const int* __restrict__ batch,
                          const float* __restrict__ W,
                          const float* __restrict__ b_conv,
                          const float* __restrict__ W_out,
                          float* __restrict__ out, int N) {
    __shared__ float sW[IN_DIM * WPITCH];
    __shared__ float sb[EMB];
    __shared__ float so[EMB];
    for (int t = threadIdx.x; t < IN_DIM * EMB; t += blockDim.x) {
        int r = t / EMB, cCol = t % EMB;
        sW[r * WPITCH + cCol] = W[t];
    }
    if (threadIdx.x < EMB) {
        sb[threadIdx.x] = b_conv[threadIdx.x];
        so[threadIdx.x] = W_out[threadIdx.x];
    }
    __syncthreads();

    int i = blockIdx.x * blockDim.x + threadIdx.x;
    if (i >= N) return;

    int2 p = g_packed[i];
    float dinv = __int_as_float(p.x);
    int   xi   = p.y;
    int   cnt  = g_cnt[i];
    int   b0   = g_base[i] - cnt;        // k_build advanced base to END

    float acc[EMB];
    {
        const float* row = &sW[xi * WPITCH];
#pragma unroll
        for (int j = 0; j < EMB; j++) acc[j] = dinv * row[j];
    }
    for (int k = 0; k < cnt; k++) {
        int  s  = g_elist[b0 + k];
        int2 ps = g_packed[s];
        float ds = __int_as_float(ps.x);
        const float* row = &sW[ps.y * WPITCH];
#pragma unroll
        for (int j = 0; j < EMB; j++) acc[j] += ds * row[j];
    }

    float res = 0.f;
#pragma unroll
    for (int j = 0; j < EMB; j++)
        res += tanha(acc[j] * dinv + sb[j]) * so[j];

    atomicAdd(&out[batch[i]], res);
}

// ---------------------------------------------------------------------------
// Launch
// Inputs: 0:x[N] i32, 1:edge_index[2E] i32, 2:batch[N] i32,
//         3:W[65*32] f32, 4:b_conv[32] f32, 5:W_out[32] f32, 6:b_out[1] f32
// Output: out[G] f32
// ---------------------------------------------------------------------------
extern "C" void kernel_launch(void* const* d_in, const int* in_sizes, int n_in,
                              void* d_out, int out_size) {
    const int*   x     = (const int*)d_in[0];
    const int*   eidx  = (const int*)d_in[1];
    const int*   batch = (const int*)d_in[2];
    const float* W     = (const float*)d_in[3];
    const float* bconv = (const float*)d_in[4];
    const float* Wout  = (const float*)d_in[5];
    const float* bout  = (const float*)d_in[6];
    float* out = (float*)d_out;

    int N = in_sizes[0];
    int E = in_sizes[1] / 2;
    int G = out_size;

    const int* src = eidx;
    const int* dst = eidx + E;

    int initN = N > G ? N : G;
    int nbN   = (N + TB - 1) / TB;
    int nbE4  = ((E + 3) / 4 + TB - 1) / TB;

    k_init   <<<(initN + TB - 1) / TB, TB>>>(out, bout, N, G);
    k_deg    <<<nbE4, TB>>>(dst, E);
    k_alloc  <<<nbN, TB>>>(x, N);
    k_build  <<<nbE4, TB>>>(src, dst, E);
    k_aggpool<<<nbN, TB>>>(batch, W, bconv, Wout, out, N);
}